// round 12
// baseline (speedup 1.0000x reference)
#include <cuda_runtime.h>
#include <cuda_fp16.h>
#include <cuda_pipeline.h>

// SAG: CSR SpMM neighbor aggregation, deg=16, D=48, fp32 in/out.
//
// R11: the occ x MLP product is pinned by the register file (~1.5 in-flight
// LDGs/warp at 32 regs -> all LDG variants stuck at ~20us). Fix: stage each
// node's 16 fp16 rows (1536B) into smem with THREE warp-wide 16B cp.async.cg
// ops (the fast path; R9's failure was the 8B .ca path). LDGSTS has no dest
// register -> ~84KB in flight per SM, L2 latency fully covered, L2-sector
// floor (~15us) binds. Consume from smem conflict-free, fp16 two-tree
// accumulation (rel_err ~5e-4). Warp per node, 8 nodes/block, 12.3KB smem.

#define N_CAP   100000
#define D_FEAT  48
#define ROW_B   96                       // fp16 row bytes (96 % 16 == 0)
#define NODE_B  (16 * ROW_B)             // 1536 B staged per node

__device__ __align__(16) char g_Xh[(size_t)N_CAP * ROW_B];   // 9.6 MB scratch

// ---- pre-pass: fp32 [n,48] -> fp16 [n,48] (contiguous, vectorized) ---------
__global__ void convert_kernel(const float4* __restrict__ X4, int total4)
{
    int t = blockIdx.x * blockDim.x + threadIdx.x;   // one float4 -> one uint2
    if (t >= total4) return;
    const float4 f = __ldg(X4 + t);
    const __half2 a = __floats2half2_rn(f.x, f.y);
    const __half2 b = __floats2half2_rn(f.z, f.w);
    uint2 v;
    v.x = *reinterpret_cast<const unsigned int*>(&a);
    v.y = *reinterpret_cast<const unsigned int*>(&b);
    reinterpret_cast<uint2*>(g_Xh)[t] = v;
}

// ---- main: warp per node, cp.async.cg 16B staging, fp16 two-tree sum -------
__global__ __launch_bounds__(256, 8)
void sag_fp16_kernel(const int* __restrict__ row_pointers,
                     const int* __restrict__ column_index,
                     float* __restrict__ out,
                     int n_nodes)
{
    __shared__ __align__(16) char stage[8 * NODE_B];   // 12288 B

    const int wid  = threadIdx.x >> 5;                 // warp in block: 0..7
    const int lane = threadIdx.x & 31;
    const int node = blockIdx.x * 8 + wid;
    if (node >= n_nodes) return;

    const int base = row_pointers[node];
    const int deg  = row_pointers[node + 1] - base;

    // lanes 0..15 hold the 16 edge indices (coalesced 64B load)
    int my_idx = 0;
    if (lane < 16 && lane < deg) my_idx = column_index[base + lane];

    char* const slot = stage + wid * NODE_B;
    const int lc = (lane < 24) ? lane : 23;            // clamp, branch-free

    if (deg == 16) {
        // Stage all 16 rows: 3 warp-wide 16B copies. Lane covers bytes
        // [byte, byte+16) of the 1536B slot; edge e = byte/96 (exact via
        // mul-high by 683, verified for byte in {0,16,...,1520}).
        #pragma unroll
        for (int it = 0; it < 3; ++it) {
            const int byte = it * 512 + lane * 16;
            const int e    = (byte * 683) >> 16;       // byte / 96
            const int off  = byte - e * 96;
            const int idx  = __shfl_sync(0xffffffffu, my_idx, e);
            __pipeline_memcpy_async(slot + byte,
                                    g_Xh + (size_t)idx * ROW_B + off, 16);
        }
        __pipeline_commit();
        __pipeline_wait_prior(0);
        __syncwarp();                                  // all lanes' copies visible

        // Two independent fp16 trees (edges 0-7, 8-15) combined in fp32.
        // Lane lc owns half2 slot lc (4B) of each 96B row; conflict-free LDS.
        __half2 t0 = __float2half2_rn(0.f), t1 = __float2half2_rn(0.f);
        #pragma unroll
        for (int e = 0; e < 16; ++e) {
            const __half2 h = *reinterpret_cast<const __half2*>(slot + e * ROW_B + lc * 4);
            if (e < 8) t0 = __hadd2(t0, h);
            else       t1 = __hadd2(t1, h);
        }

        if (lane < 24) {
            const float2 f0 = __half22float2(t0);
            const float2 f1 = __half22float2(t1);
            reinterpret_cast<float2*>(out)[node * 24 + lane] =
                make_float2(f0.x + f1.x, f0.y + f1.y);
        }
    } else {
        // Generic fallback (never taken here): direct LDG fp32 accumulate.
        float ax = 0.f, ay = 0.f;
        for (int e = 0; e < deg; ++e) {
            int idx = (e < 16) ? __shfl_sync(0xffffffffu, my_idx, e)
                               : column_index[base + e];
            const __half2 h = *reinterpret_cast<const __half2*>(
                g_Xh + (size_t)idx * ROW_B + lc * 4);
            const float2 f = __half22float2(h);
            ax += f.x; ay += f.y;
        }
        if (lane < 24) {
            reinterpret_cast<float2*>(out)[node * 24 + lane] = make_float2(ax, ay);
        }
    }
}

// ---- fp32 fallback (only if n exceeds scratch capacity) --------------------
__global__ __launch_bounds__(256, 8)
void sag_fp32_kernel(const float* __restrict__ X,
                     const int* __restrict__ row_pointers,
                     const int* __restrict__ column_index,
                     float* __restrict__ out,
                     int n_nodes)
{
    const int tid  = blockIdx.x * blockDim.x + threadIdx.x;
    const int node = tid >> 4;
    const int lane = tid & 15;
    if (node >= n_nodes) return;

    const int base = row_pointers[node];
    const int deg  = row_pointers[node + 1] - base;
    int my_idx = 0;
    if (lane < deg) my_idx = column_index[base + lane];

    float a0 = 0.f, a1 = 0.f, a2 = 0.f;
    for (int e = 0; e < deg; ++e) {
        int idx = (e < 16) ? __shfl_sync(0xffffffffu, my_idx, e, 16)
                           : column_index[base + e];
        const float* row = X + (size_t)idx * D_FEAT;
        a0 += __ldg(row + lane);
        a1 += __ldg(row + lane + 16);
        a2 += __ldg(row + lane + 32);
    }
    float* orow = out + (size_t)node * D_FEAT;
    orow[lane] = a0; orow[lane + 16] = a1; orow[lane + 32] = a2;
}

extern "C" void kernel_launch(void* const* d_in, const int* in_sizes, int n_in,
                              void* d_out, int out_size)
{
    const float* X   = (const float*)d_in[0];
    const int*   rp  = (const int*)d_in[1];
    const int*   col = (const int*)d_in[2];
    float*       out = (float*)d_out;

    const int n_nodes = in_sizes[1] - 1;

    if (n_nodes <= N_CAP) {
        {
            const int total4 = n_nodes * (D_FEAT / 4);      // 1.2M float4
            const int threads = 256;
            convert_kernel<<<(total4 + threads - 1) / threads, threads>>>(
                reinterpret_cast<const float4*>(X), total4);
        }
        {
            const int threads = 256;                         // 8 nodes / block
            const int blocks = (n_nodes + 7) / 8;
            sag_fp16_kernel<<<blocks, threads>>>(rp, col, out, n_nodes);
        }
    } else {
        const int threads = 256;
        const int blocks = (n_nodes * 16 + threads - 1) / threads;
        sag_fp32_kernel<<<blocks, threads>>>(X, rp, col, out, n_nodes);
    }
}

// round 13
// speedup vs baseline: 1.0894x; 1.0894x over previous
#include <cuda_runtime.h>
#include <cuda_fp16.h>

// SAG: CSR SpMM neighbor aggregation, deg=16, D=48, fp32 in/out.
//
// R12: every LDG variant stalls at ~20us because ptxas at 32 regs pipelines
// the gather only ~2 deep -> ~160 in-flight LDG.64/SM, exactly the Little's-
// law number for 600cyc L2 latency at 40k cyc. Fix: FORCE pipeline depth 16 —
// load all 16 rows into an explicit int2[16] register array before any
// accumulation. Data regs: 32; addr regs die at issue; total ~52-56 regs ->
// __launch_bounds__(256,4): occ ~50% (32 warps/SM) but 32x16=512 loads in
// flight >> the ~160 needed -> the ~12.5us L2-sector floor finally binds.
// Unpadded 96B fp16 rows (R10 showed padding doesn't help), 2 nodes/warp,
// branch-free clamp, fp16 two-tree accumulation (rel_err ~5e-4 < 1e-3).

#define N_CAP   100000
#define D_FEAT  48
#define ROW_I2  12            // 96 B row = 12 int2 (4 halves each)

__device__ __align__(16) __half2 g_Xh[(size_t)N_CAP * 24];   // 9.6 MB scratch

// ---- pre-pass: fp32 [n,48] -> fp16 [n,48] (contiguous, vectorized) ---------
__global__ void convert_kernel(const float4* __restrict__ X4, int total4)
{
    int t = blockIdx.x * blockDim.x + threadIdx.x;   // one float4 -> one uint2
    if (t >= total4) return;
    const float4 f = __ldg(X4 + t);
    const __half2 a = __floats2half2_rn(f.x, f.y);
    const __half2 b = __floats2half2_rn(f.z, f.w);
    uint2 v;
    v.x = *reinterpret_cast<const unsigned int*>(&a);
    v.y = *reinterpret_cast<const unsigned int*>(&b);
    reinterpret_cast<uint2*>(g_Xh)[t] = v;
}

// ---- main: 2 nodes/warp, explicit 16-deep load pipeline, fp16 two-tree -----
__global__ __launch_bounds__(256, 4)
void sag_fp16_kernel(const int* __restrict__ row_pointers,
                     const int* __restrict__ column_index,
                     float* __restrict__ out,
                     int n_nodes)
{
    const int sub  = threadIdx.x & 15;                  // lane within node group
    const int node = ((blockIdx.x * blockDim.x + threadIdx.x) >> 4);
    if (node >= n_nodes) return;

    const int base = row_pointers[node];
    const int deg  = row_pointers[node + 1] - base;

    // sub-lane e holds edge e's neighbor index (coalesced)
    int my_idx = 0;
    if (sub < deg) my_idx = column_index[base + sub];

    // Lanes 12-15 duplicate lane 11's slot: same cache lines, zero extra
    // traffic, results discarded at store time. Branch-free loop body.
    const int subc = (sub < ROW_I2) ? sub : (ROW_I2 - 1);
    const int2* __restrict__ Xi2 = reinterpret_cast<const int2*>(g_Xh);

    if (deg == 16) {
        // Phase 1: issue ALL 16 gathers into a register array (depth-16 MLP,
        // no consumer between loads -> ptxas front-batches the LDGs).
        int2 v[16];
        #pragma unroll
        for (int e = 0; e < 16; ++e) {
            const int idx = __shfl_sync(0xffffffffu, my_idx, e, 16);
            v[e] = __ldg(Xi2 + (idx * ROW_I2 + subc));
        }

        // Phase 2: two independent fp16 trees (edges 0-7, 8-15), fp32 combine.
        __half2 t0a = __float2half2_rn(0.f), t0b = __float2half2_rn(0.f);
        __half2 t1a = __float2half2_rn(0.f), t1b = __float2half2_rn(0.f);
        #pragma unroll
        for (int e = 0; e < 8; ++e) {
            t0a = __hadd2(t0a, *reinterpret_cast<const __half2*>(&v[e].x));
            t0b = __hadd2(t0b, *reinterpret_cast<const __half2*>(&v[e].y));
            t1a = __hadd2(t1a, *reinterpret_cast<const __half2*>(&v[e + 8].x));
            t1b = __hadd2(t1b, *reinterpret_cast<const __half2*>(&v[e + 8].y));
        }

        if (sub < ROW_I2) {
            const float2 f0 = __half22float2(t0a);
            const float2 f1 = __half22float2(t0b);
            const float2 g0 = __half22float2(t1a);
            const float2 g1 = __half22float2(t1b);
            reinterpret_cast<float4*>(out)[node * ROW_I2 + sub] =
                make_float4(f0.x + g0.x, f0.y + g0.y, f1.x + g1.x, f1.y + g1.y);
        }
    } else {
        // Generic fallback (never taken here): fp32 accumulate.
        float a0 = 0.f, a1 = 0.f, a2 = 0.f, a3 = 0.f;
        for (int e = 0; e < deg; ++e) {
            int idx = (e < 16) ? __shfl_sync(0xffffffffu, my_idx, e, 16)
                               : column_index[base + e];
            const int2 w = __ldg(Xi2 + (idx * ROW_I2 + subc));
            const float2 f0 = __half22float2(*reinterpret_cast<const __half2*>(&w.x));
            const float2 f1 = __half22float2(*reinterpret_cast<const __half2*>(&w.y));
            a0 += f0.x; a1 += f0.y; a2 += f1.x; a3 += f1.y;
        }
        if (sub < ROW_I2) {
            reinterpret_cast<float4*>(out)[node * ROW_I2 + sub] =
                make_float4(a0, a1, a2, a3);
        }
    }
}

// ---- fp32 fallback (only if n exceeds scratch capacity) --------------------
__global__ __launch_bounds__(256, 8)
void sag_fp32_kernel(const float* __restrict__ X,
                     const int* __restrict__ row_pointers,
                     const int* __restrict__ column_index,
                     float* __restrict__ out,
                     int n_nodes)
{
    const int tid  = blockIdx.x * blockDim.x + threadIdx.x;
    const int node = tid >> 4;
    const int lane = tid & 15;
    if (node >= n_nodes) return;

    const int base = row_pointers[node];
    const int deg  = row_pointers[node + 1] - base;
    int my_idx = 0;
    if (lane < deg) my_idx = column_index[base + lane];

    float a0 = 0.f, a1 = 0.f, a2 = 0.f;
    for (int e = 0; e < deg; ++e) {
        int idx = (e < 16) ? __shfl_sync(0xffffffffu, my_idx, e, 16)
                           : column_index[base + e];
        const float* row = X + (size_t)idx * D_FEAT;
        a0 += __ldg(row + lane);
        a1 += __ldg(row + lane + 16);
        a2 += __ldg(row + lane + 32);
    }
    float* orow = out + (size_t)node * D_FEAT;
    orow[lane] = a0; orow[lane + 16] = a1; orow[lane + 32] = a2;
}

extern "C" void kernel_launch(void* const* d_in, const int* in_sizes, int n_in,
                              void* d_out, int out_size)
{
    const float* X   = (const float*)d_in[0];
    const int*   rp  = (const int*)d_in[1];
    const int*   col = (const int*)d_in[2];
    float*       out = (float*)d_out;

    const int n_nodes = in_sizes[1] - 1;

    if (n_nodes <= N_CAP) {
        {
            const int total4 = n_nodes * (D_FEAT / 4);      // 1.2M float4
            const int threads = 256;
            convert_kernel<<<(total4 + threads - 1) / threads, threads>>>(
                reinterpret_cast<const float4*>(X), total4);
        }
        {
            const int threads = 256;                         // 16 nodes / block
            const int blocks = (n_nodes + 15) / 16;
            sag_fp16_kernel<<<blocks, threads>>>(rp, col, out, n_nodes);
        }
    } else {
        const int threads = 256;
        const int blocks = (n_nodes * 16 + threads - 1) / threads;
        sag_fp32_kernel<<<blocks, threads>>>(X, rp, col, out, n_nodes);
    }
}

// round 14
// speedup vs baseline: 1.1202x; 1.0283x over previous
#include <cuda_runtime.h>
#include <cuda_fp16.h>

// SAG: CSR SpMM neighbor aggregation, deg=16, D=48, fp32 in/out.
//
// R13: all LDG.64 variants wall at ~143 sectors/cyc; R1's contiguous-burst
// pattern hit the ~197/cyc LTS cap. Hypothesis: many small 2-line requests
// underutilize the L1tex/LTS path. Fix: pad fp16 rows to 128B and gather one
// FULL LINE per row with LDG.128 (8 lanes x 16B). Each warp instruction
// covers 4 nodes = 4 single-line wavefronts of 4 contiguous sectors (R1's
// burst profile at half the bytes). 4 nodes/warp, 1.75 instr/edge, all 32
// lanes active, ~28 regs -> full occupancy. fp16 two-tree accumulation
// (rel_err ~5e-4 < 1e-3). Sectors 7.2M @ ~197/cyc -> main ~17-18us.

#define N_CAP   100000
#define D_FEAT  48
#define ROW_I4  8             // padded row: 128 B = 8 int4 (8 halves each)
#define USED_I4 6             // 96 B real data

__device__ __align__(128) __half2 g_Xh[(size_t)N_CAP * 32];   // 12.8 MB scratch

// ---- pre-pass: fp32 [n,48] -> fp16 [n,64pad]; one thread per int4 slot -----
__global__ void convert_kernel(const float4* __restrict__ X4, int n_nodes)
{
    const int t = blockIdx.x * blockDim.x + threadIdx.x;    // int4 slot
    const int total = n_nodes * ROW_I4;
    if (t >= total) return;
    const int row = t >> 3;
    const int c   = t & 7;
    int4 v = make_int4(0, 0, 0, 0);
    if (c < USED_I4) {
        // slot c covers floats [8c, 8c+8) of the row = two float4
        const float4 f0 = __ldg(X4 + row * 12 + 2 * c);
        const float4 f1 = __ldg(X4 + row * 12 + 2 * c + 1);
        const __half2 a = __floats2half2_rn(f0.x, f0.y);
        const __half2 b = __floats2half2_rn(f0.z, f0.w);
        const __half2 cc = __floats2half2_rn(f1.x, f1.y);
        const __half2 d = __floats2half2_rn(f1.z, f1.w);
        v.x = *reinterpret_cast<const int*>(&a);
        v.y = *reinterpret_cast<const int*>(&b);
        v.z = *reinterpret_cast<const int*>(&cc);
        v.w = *reinterpret_cast<const int*>(&d);
    }
    reinterpret_cast<int4*>(g_Xh)[t] = v;
}

// ---- main: 4 nodes/warp, 8 lanes/node, LDG.128 full-line gather ------------
__global__ __launch_bounds__(256, 8)
void sag_fp16_kernel(const int* __restrict__ row_pointers,
                     const int* __restrict__ column_index,
                     float* __restrict__ out,
                     int n_nodes)
{
    const int lane8 = threadIdx.x & 7;                   // lane within node group
    const int node  = (blockIdx.x * blockDim.x + threadIdx.x) >> 3;
    if (node >= n_nodes) return;

    const int base = row_pointers[node];
    const int deg  = row_pointers[node + 1] - base;

    const int4* __restrict__ X4 = reinterpret_cast<const int4*>(g_Xh);

    if (deg == 16) {
        // lane8 l holds edge indices (2l, 2l+1) as one int2 (coalesced 64B/group)
        const int2 ip = *reinterpret_cast<const int2*>(column_index + base + 2 * lane8);

        // Two independent fp16 trees (edges 0-7, 8-15), 4 half2 each.
        __half2 t0[4], t1[4];
        #pragma unroll
        for (int k = 0; k < 4; ++k) {
            t0[k] = __float2half2_rn(0.f);
            t1[k] = __float2half2_rn(0.f);
        }

        #pragma unroll
        for (int e = 0; e < 16; ++e) {
            const int idx = __shfl_sync(0xffffffffu, (e & 1) ? ip.y : ip.x, e >> 1, 8);
            const int4 v = __ldg(X4 + ((idx << 3) + lane8));   // one full line/row
            const __half2 h0 = *reinterpret_cast<const __half2*>(&v.x);
            const __half2 h1 = *reinterpret_cast<const __half2*>(&v.y);
            const __half2 h2 = *reinterpret_cast<const __half2*>(&v.z);
            const __half2 h3 = *reinterpret_cast<const __half2*>(&v.w);
            if (e < 8) {
                t0[0] = __hadd2(t0[0], h0); t0[1] = __hadd2(t0[1], h1);
                t0[2] = __hadd2(t0[2], h2); t0[3] = __hadd2(t0[3], h3);
            } else {
                t1[0] = __hadd2(t1[0], h0); t1[1] = __hadd2(t1[1], h1);
                t1[2] = __hadd2(t1[2], h2); t1[3] = __hadd2(t1[3], h3);
            }
        }

        // lane8 owns features [8*lane8, 8*lane8+8); lanes 6,7 hold padding.
        if (lane8 < USED_I4) {
            float f[8];
            #pragma unroll
            for (int k = 0; k < 4; ++k) {
                const float2 a = __half22float2(t0[k]);
                const float2 b = __half22float2(t1[k]);
                f[2 * k]     = a.x + b.x;
                f[2 * k + 1] = a.y + b.y;
            }
            float4* orow = reinterpret_cast<float4*>(out) + node * 12 + 2 * lane8;
            orow[0] = make_float4(f[0], f[1], f[2], f[3]);
            orow[1] = make_float4(f[4], f[5], f[6], f[7]);
        }
    } else {
        // Generic fallback (never taken here): scalar fp32 accumulate.
        float f[8] = {0.f, 0.f, 0.f, 0.f, 0.f, 0.f, 0.f, 0.f};
        for (int e = 0; e < deg; ++e) {
            const int idx = column_index[base + e];
            const int4 v = __ldg(X4 + ((idx << 3) + lane8));
            const __half2* h = reinterpret_cast<const __half2*>(&v);
            #pragma unroll
            for (int k = 0; k < 4; ++k) {
                const float2 a = __half22float2(h[k]);
                f[2 * k] += a.x; f[2 * k + 1] += a.y;
            }
        }
        if (lane8 < USED_I4) {
            float4* orow = reinterpret_cast<float4*>(out) + node * 12 + 2 * lane8;
            orow[0] = make_float4(f[0], f[1], f[2], f[3]);
            orow[1] = make_float4(f[4], f[5], f[6], f[7]);
        }
    }
}

// ---- fp32 fallback (only if n exceeds scratch capacity) --------------------
__global__ __launch_bounds__(256, 8)
void sag_fp32_kernel(const float* __restrict__ X,
                     const int* __restrict__ row_pointers,
                     const int* __restrict__ column_index,
                     float* __restrict__ out,
                     int n_nodes)
{
    const int tid  = blockIdx.x * blockDim.x + threadIdx.x;
    const int node = tid >> 4;
    const int lane = tid & 15;
    if (node >= n_nodes) return;

    const int base = row_pointers[node];
    const int deg  = row_pointers[node + 1] - base;
    int my_idx = 0;
    if (lane < deg) my_idx = column_index[base + lane];

    float a0 = 0.f, a1 = 0.f, a2 = 0.f;
    for (int e = 0; e < deg; ++e) {
        int idx = (e < 16) ? __shfl_sync(0xffffffffu, my_idx, e, 16)
                           : column_index[base + e];
        const float* row = X + (size_t)idx * D_FEAT;
        a0 += __ldg(row + lane);
        a1 += __ldg(row + lane + 16);
        a2 += __ldg(row + lane + 32);
    }
    float* orow = out + (size_t)node * D_FEAT;
    orow[lane] = a0; orow[lane + 16] = a1; orow[lane + 32] = a2;
}

extern "C" void kernel_launch(void* const* d_in, const int* in_sizes, int n_in,
                              void* d_out, int out_size)
{
    const float* X   = (const float*)d_in[0];
    const int*   rp  = (const int*)d_in[1];
    const int*   col = (const int*)d_in[2];
    float*       out = (float*)d_out;

    const int n_nodes = in_sizes[1] - 1;

    if (n_nodes <= N_CAP) {
        {
            const int total = n_nodes * ROW_I4;              // 800k int4 slots
            const int threads = 256;
            convert_kernel<<<(total + threads - 1) / threads, threads>>>(
                reinterpret_cast<const float4*>(X), n_nodes);
        }
        {
            const int threads = 256;                         // 32 nodes / block
            const int blocks = (n_nodes + 31) / 32;
            sag_fp16_kernel<<<blocks, threads>>>(rp, col, out, n_nodes);
        }
    } else {
        const int threads = 256;
        const int blocks = (n_nodes * 16 + threads - 1) / threads;
        sag_fp32_kernel<<<blocks, threads>>>(X, rp, col, out, n_nodes);
    }
}